// round 5
// baseline (speedup 1.0000x reference)
#include <cuda_runtime.h>
#include <cuda_bf16.h>
#include <cstdint>

#define N_NODES 65536
#define N_EDGES 1048576
#define IN_F 64
#define OUT_F 64

// ---- scratch (static __device__, no allocation) ----
__device__ float g_support[(size_t)N_NODES * OUT_F];   // 16 MB
__device__ uint2 g_sorted[N_EDGES];                    // 8 MB  (x=col bits, y=val bits)
__device__ int   g_counts[N_NODES];                    // degree per dest node
__device__ int   g_rowptr[N_NODES];                    // CSR start per dest node
__device__ int   g_cursor[N_NODES];                    // placement cursors

// ---------------------------------------------------------------------------
// support = X @ W   (one thread per row, W broadcast from smem)
// ---------------------------------------------------------------------------
__global__ void __launch_bounds__(256)
gemm_kernel(const float* __restrict__ X, const float* __restrict__ W,
            float* __restrict__ S, int n_nodes)
{
    __shared__ float sW[IN_F * OUT_F];
    for (int i = threadIdx.x; i < IN_F * OUT_F; i += 256)
        sW[i] = W[i];
    __syncthreads();

    int row = blockIdx.x * 256 + threadIdx.x;
    if (row >= n_nodes) return;

    float acc[OUT_F];
#pragma unroll
    for (int j = 0; j < OUT_F; j++) acc[j] = 0.0f;

    const float4* xr = reinterpret_cast<const float4*>(X + (size_t)row * IN_F);
#pragma unroll 4
    for (int k4 = 0; k4 < IN_F / 4; k4++) {
        float4 x = xr[k4];
        int k = k4 * 4;
        const float4* w0 = reinterpret_cast<const float4*>(sW + (k + 0) * OUT_F);
        const float4* w1 = reinterpret_cast<const float4*>(sW + (k + 1) * OUT_F);
        const float4* w2 = reinterpret_cast<const float4*>(sW + (k + 2) * OUT_F);
        const float4* w3 = reinterpret_cast<const float4*>(sW + (k + 3) * OUT_F);
#pragma unroll
        for (int j4 = 0; j4 < OUT_F / 4; j4++) {
            float4 a = w0[j4], b = w1[j4], c = w2[j4], d = w3[j4];
            acc[j4 * 4 + 0] += x.x * a.x + x.y * b.x + x.z * c.x + x.w * d.x;
            acc[j4 * 4 + 1] += x.x * a.y + x.y * b.y + x.z * c.y + x.w * d.y;
            acc[j4 * 4 + 2] += x.x * a.z + x.y * b.z + x.z * c.z + x.w * d.z;
            acc[j4 * 4 + 3] += x.x * a.w + x.y * b.w + x.z * c.w + x.w * d.w;
        }
    }

    float4* sr = reinterpret_cast<float4*>(S + (size_t)row * OUT_F);
#pragma unroll
    for (int j4 = 0; j4 < OUT_F / 4; j4++) {
        float4 v = make_float4(acc[j4*4+0], acc[j4*4+1], acc[j4*4+2], acc[j4*4+3]);
        sr[j4] = v;
    }
}

// ---------------------------------------------------------------------------
// CSR build step 1: zero degree counters
// ---------------------------------------------------------------------------
__global__ void __launch_bounds__(256)
zero_counts_kernel(int* __restrict__ counts, int n)
{
    int i = blockIdx.x * 256 + threadIdx.x;
    if (i < n) counts[i] = 0;
}

// ---------------------------------------------------------------------------
// CSR build step 2: histogram of destination rows (REDG, no return needed)
// ---------------------------------------------------------------------------
__global__ void __launch_bounds__(256)
hist_kernel(const int* __restrict__ rows, int* __restrict__ counts, int n_edges)
{
    int e = blockIdx.x * 256 + threadIdx.x;
    if (e < n_edges) atomicAdd(&counts[rows[e]], 1);
}

// ---------------------------------------------------------------------------
// CSR build step 3: exclusive prefix sum over 65536 counts (single block).
// Thread t owns counts[t*64 .. t*64+63]; two passes over its chunk.
// Writes row_ptr and initializes cursor = row_ptr.
// ---------------------------------------------------------------------------
__global__ void __launch_bounds__(1024)
scan_kernel(const int* __restrict__ counts, int* __restrict__ rowptr,
            int* __restrict__ cursor, int n)
{
    __shared__ int ssum[1024];
    int t = threadIdx.x;
    int base = t * 64;

    int chunk = 0;
#pragma unroll 8
    for (int i = 0; i < 64; i++) chunk += counts[base + i];
    ssum[t] = chunk;
    __syncthreads();

    // Hillis–Steele inclusive scan over 1024 partials
    for (int d = 1; d < 1024; d <<= 1) {
        int add = (t >= d) ? ssum[t - d] : 0;
        __syncthreads();
        ssum[t] += add;
        __syncthreads();
    }
    int offset = ssum[t] - chunk;   // exclusive prefix of this chunk

    int run = offset;
#pragma unroll 8
    for (int i = 0; i < 64; i++) {
        rowptr[base + i] = run;
        cursor[base + i] = run;
        run += counts[base + i];
    }
}

// ---------------------------------------------------------------------------
// CSR build step 4: place each edge (col, val) into its dest bucket.
// ---------------------------------------------------------------------------
__global__ void __launch_bounds__(256)
place_kernel(const int* __restrict__ rows, const int* __restrict__ cols,
             const float* __restrict__ vals, int* __restrict__ cursor,
             uint2* __restrict__ sorted, int n_edges)
{
    int e = blockIdx.x * 256 + threadIdx.x;
    if (e >= n_edges) return;
    int r = rows[e];
    int pos = atomicAdd(&cursor[r], 1);
    sorted[pos] = make_uint2((unsigned)cols[e], __float_as_uint(vals[e]));
}

// ---------------------------------------------------------------------------
// Gather: 16 threads per destination node; thread q owns output float4 q.
// Half-warp cooperatively stages 16 edges, broadcasts via shfl, gathers
// coalesced 256B rows of support, accumulates in registers, writes
// relu(acc + bias) exactly once. No atomics.
// ---------------------------------------------------------------------------
__global__ void __launch_bounds__(256)
gather_kernel(const int* __restrict__ rowptr, const int* __restrict__ counts,
              const uint2* __restrict__ sorted, const float* __restrict__ S,
              const float* __restrict__ bias, float* __restrict__ out,
              int n_nodes)
{
    int idx  = blockIdx.x * 256 + threadIdx.x;
    int node = idx >> 4;
    if (node >= n_nodes) return;
    int q    = idx & 15;
    int lane = threadIdx.x & 31;
    unsigned hmask = (lane < 16) ? 0x0000FFFFu : 0xFFFF0000u;
    int hbase = lane & 16;

    int start = rowptr[node];
    int deg   = counts[node];

    const float4* S4 = reinterpret_cast<const float4*>(S);
    float4 acc = make_float4(0.f, 0.f, 0.f, 0.f);

    for (int b = 0; b < deg; b += 16) {
        int m = deg - b; if (m > 16) m = 16;
        uint2 e = make_uint2(0u, 0u);
        if (q < m) e = sorted[start + b + q];
        for (int j = 0; j < m; j++) {
            int   col = (int)__shfl_sync(hmask, e.x, hbase | j);
            float v   = __uint_as_float(__shfl_sync(hmask, e.y, hbase | j));
            float4 s  = S4[(size_t)col * (OUT_F / 4) + q];
            acc.x += v * s.x; acc.y += v * s.y;
            acc.z += v * s.z; acc.w += v * s.w;
        }
    }

    float4 bb = reinterpret_cast<const float4*>(bias)[q];
    float4 r;
    r.x = fmaxf(acc.x + bb.x, 0.f);
    r.y = fmaxf(acc.y + bb.y, 0.f);
    r.z = fmaxf(acc.z + bb.z, 0.f);
    r.w = fmaxf(acc.w + bb.w, 0.f);
    reinterpret_cast<float4*>(out)[(size_t)node * (OUT_F / 4) + q] = r;
}

extern "C" void kernel_launch(void* const* d_in, const int* in_sizes, int n_in,
                              void* d_out, int out_size)
{
    const float* X    = (const float*)d_in[0];
    const int*   rows = (const int*)  d_in[1];
    const int*   cols = (const int*)  d_in[2];
    const float* vals = (const float*)d_in[3];
    const float* W    = (const float*)d_in[4];
    const float* bias = (const float*)d_in[5];
    float*       out  = (float*)d_out;

    int n_nodes = in_sizes[0] / IN_F;
    int n_edges = in_sizes[1];

    float* S;      cudaGetSymbolAddress((void**)&S,      g_support);
    uint2* sorted; cudaGetSymbolAddress((void**)&sorted, g_sorted);
    int*   counts; cudaGetSymbolAddress((void**)&counts, g_counts);
    int*   rowptr; cudaGetSymbolAddress((void**)&rowptr, g_rowptr);
    int*   cursor; cudaGetSymbolAddress((void**)&cursor, g_cursor);

    // CSR build
    zero_counts_kernel<<<(n_nodes + 255) / 256, 256>>>(counts, n_nodes);
    hist_kernel<<<(n_edges + 255) / 256, 256>>>(rows, counts, n_edges);
    scan_kernel<<<1, 1024>>>(counts, rowptr, cursor, n_nodes);
    place_kernel<<<(n_edges + 255) / 256, 256>>>(rows, cols, vals, cursor,
                                                 sorted, n_edges);

    // dense: support = X @ W
    gemm_kernel<<<(n_nodes + 255) / 256, 256>>>(X, W, S, n_nodes);

    // fused gather + bias + relu
    long long total = (long long)n_nodes * 16;
    gather_kernel<<<(int)((total + 255) / 256), 256>>>(rowptr, counts, sorted,
                                                       S, bias, out, n_nodes);
}

// round 7
// speedup vs baseline: 2.0860x; 2.0860x over previous
#include <cuda_runtime.h>
#include <cuda_bf16.h>
#include <cstdint>

#define N_NODES 65536
#define N_EDGES 1048576
#define IN_F 64
#define OUT_F 64

// ---- scratch (static __device__, no allocation) ----
__device__ float g_support[(size_t)N_NODES * OUT_F];   // 16 MB
__device__ uint2 g_sorted[N_EDGES];                    // 8 MB  (x=col, y=val bits)
__device__ int   g_counts[N_NODES];
__device__ int   g_rowptr[N_NODES];
__device__ int   g_cursor[N_NODES];

// ---------------------------------------------------------------------------
// support = X @ W   (one thread per row, W broadcast from smem)
// ---------------------------------------------------------------------------
__global__ void __launch_bounds__(256)
gemm_kernel(const float* __restrict__ X, const float* __restrict__ W,
            float* __restrict__ S, int n_nodes)
{
    __shared__ float sW[IN_F * OUT_F];
    for (int i = threadIdx.x; i < IN_F * OUT_F; i += 256)
        sW[i] = W[i];
    __syncthreads();

    int row = blockIdx.x * 256 + threadIdx.x;
    if (row >= n_nodes) return;

    float acc[OUT_F];
#pragma unroll
    for (int j = 0; j < OUT_F; j++) acc[j] = 0.0f;

    const float4* xr = reinterpret_cast<const float4*>(X + (size_t)row * IN_F);
#pragma unroll 4
    for (int k4 = 0; k4 < IN_F / 4; k4++) {
        float4 x = xr[k4];
        int k = k4 * 4;
        const float4* w0 = reinterpret_cast<const float4*>(sW + (k + 0) * OUT_F);
        const float4* w1 = reinterpret_cast<const float4*>(sW + (k + 1) * OUT_F);
        const float4* w2 = reinterpret_cast<const float4*>(sW + (k + 2) * OUT_F);
        const float4* w3 = reinterpret_cast<const float4*>(sW + (k + 3) * OUT_F);
#pragma unroll
        for (int j4 = 0; j4 < OUT_F / 4; j4++) {
            float4 a = w0[j4], b = w1[j4], c = w2[j4], d = w3[j4];
            acc[j4 * 4 + 0] += x.x * a.x + x.y * b.x + x.z * c.x + x.w * d.x;
            acc[j4 * 4 + 1] += x.x * a.y + x.y * b.y + x.z * c.y + x.w * d.y;
            acc[j4 * 4 + 2] += x.x * a.z + x.y * b.z + x.z * c.z + x.w * d.z;
            acc[j4 * 4 + 3] += x.x * a.w + x.y * b.w + x.z * c.w + x.w * d.w;
        }
    }

    float4* sr = reinterpret_cast<float4*>(S + (size_t)row * OUT_F);
#pragma unroll
    for (int j4 = 0; j4 < OUT_F / 4; j4++)
        sr[j4] = make_float4(acc[j4*4+0], acc[j4*4+1], acc[j4*4+2], acc[j4*4+3]);
}

// ---------------------------------------------------------------------------
// zero degree counters
// ---------------------------------------------------------------------------
__global__ void __launch_bounds__(256)
zero_counts_kernel(int* __restrict__ counts, int n)
{
    int i = blockIdx.x * 256 + threadIdx.x;
    if (i < n) counts[i] = 0;
}

// ---------------------------------------------------------------------------
// histogram of destination rows (RED, no return value used)
// ---------------------------------------------------------------------------
__global__ void __launch_bounds__(256)
hist_kernel(const int* __restrict__ rows, int* __restrict__ counts, int n_edges)
{
    int e = blockIdx.x * 256 + threadIdx.x;
    if (e < n_edges) atomicAdd(&counts[rows[e]], 1);
}

// ---------------------------------------------------------------------------
// exclusive prefix sum over 65536 counts. Single block, but vectorized:
// thread t loads its 64 counts as 16 independent int4 (MLP high, L2-resident),
// Hillis–Steele over 1024 partials, then emits rowptr/cursor.
// ---------------------------------------------------------------------------
__global__ void __launch_bounds__(1024)
scan_kernel(const int* __restrict__ counts, int* __restrict__ rowptr,
            int* __restrict__ cursor, int n)
{
    __shared__ int ssum[1024];
    int t = threadIdx.x;
    int base = t * 64;

    int4 c[16];
    const int4* cp = reinterpret_cast<const int4*>(counts + base);
#pragma unroll
    for (int i = 0; i < 16; i++) c[i] = cp[i];

    int chunk = 0;
#pragma unroll
    for (int i = 0; i < 16; i++) chunk += c[i].x + c[i].y + c[i].z + c[i].w;
    ssum[t] = chunk;
    __syncthreads();

    for (int d = 1; d < 1024; d <<= 1) {
        int add = (t >= d) ? ssum[t - d] : 0;
        __syncthreads();
        ssum[t] += add;
        __syncthreads();
    }
    int run = ssum[t] - chunk;   // exclusive prefix of this chunk

    int4* rp = reinterpret_cast<int4*>(rowptr + base);
    int4* up = reinterpret_cast<int4*>(cursor + base);
#pragma unroll
    for (int i = 0; i < 16; i++) {
        int4 o;
        o.x = run;           run += c[i].x;
        o.y = run;           run += c[i].y;
        o.z = run;           run += c[i].z;
        o.w = run;           run += c[i].w;
        rp[i] = o;
        up[i] = o;
    }
}

// ---------------------------------------------------------------------------
// place each edge (col, val) into its destination bucket
// ---------------------------------------------------------------------------
__global__ void __launch_bounds__(256)
place_kernel(const int* __restrict__ rows, const int* __restrict__ cols,
             const float* __restrict__ vals, int* __restrict__ cursor,
             uint2* __restrict__ sorted, int n_edges)
{
    int e = blockIdx.x * 256 + threadIdx.x;
    if (e >= n_edges) return;
    int r = rows[e];
    int pos = atomicAdd(&cursor[r], 1);
    sorted[pos] = make_uint2((unsigned)cols[e], __float_as_uint(vals[e]));
}

// ---------------------------------------------------------------------------
// Gather v2: 16 threads per destination node; thread q owns output float4 q.
// Edge records loaded directly (broadcast within the 16-group), batched 4 at
// a time BEFORE the four independent 256B support gathers -> MLP >= 4.
// Writes relu(acc + bias) exactly once. No atomics, no shfl.
// ---------------------------------------------------------------------------
__global__ void __launch_bounds__(256)
gather_kernel(const int* __restrict__ rowptr, const int* __restrict__ counts,
              const uint2* __restrict__ sorted, const float* __restrict__ S,
              const float* __restrict__ bias, float* __restrict__ out,
              int n_nodes)
{
    int idx  = blockIdx.x * 256 + threadIdx.x;
    int node = idx >> 4;
    if (node >= n_nodes) return;
    int q = idx & 15;

    int start = rowptr[node];
    int deg   = counts[node];

    const uint2*  ep = sorted + start;
    const float4* S4 = reinterpret_cast<const float4*>(S);

    float4 acc = make_float4(0.f, 0.f, 0.f, 0.f);

    int j = 0;
    for (; j + 4 <= deg; j += 4) {
        uint2 e0 = ep[j + 0];
        uint2 e1 = ep[j + 1];
        uint2 e2 = ep[j + 2];
        uint2 e3 = ep[j + 3];
        float4 s0 = S4[(size_t)e0.x * (OUT_F / 4) + q];
        float4 s1 = S4[(size_t)e1.x * (OUT_F / 4) + q];
        float4 s2 = S4[(size_t)e2.x * (OUT_F / 4) + q];
        float4 s3 = S4[(size_t)e3.x * (OUT_F / 4) + q];
        float v0 = __uint_as_float(e0.y);
        float v1 = __uint_as_float(e1.y);
        float v2 = __uint_as_float(e2.y);
        float v3 = __uint_as_float(e3.y);
        acc.x += v0 * s0.x; acc.y += v0 * s0.y; acc.z += v0 * s0.z; acc.w += v0 * s0.w;
        acc.x += v1 * s1.x; acc.y += v1 * s1.y; acc.z += v1 * s1.z; acc.w += v1 * s1.w;
        acc.x += v2 * s2.x; acc.y += v2 * s2.y; acc.z += v2 * s2.z; acc.w += v2 * s2.w;
        acc.x += v3 * s3.x; acc.y += v3 * s3.y; acc.z += v3 * s3.z; acc.w += v3 * s3.w;
    }
    for (; j < deg; j++) {
        uint2 e = ep[j];
        float4 s = S4[(size_t)e.x * (OUT_F / 4) + q];
        float v = __uint_as_float(e.y);
        acc.x += v * s.x; acc.y += v * s.y; acc.z += v * s.z; acc.w += v * s.w;
    }

    float4 bb = reinterpret_cast<const float4*>(bias)[q];
    float4 r;
    r.x = fmaxf(acc.x + bb.x, 0.f);
    r.y = fmaxf(acc.y + bb.y, 0.f);
    r.z = fmaxf(acc.z + bb.z, 0.f);
    r.w = fmaxf(acc.w + bb.w, 0.f);
    reinterpret_cast<float4*>(out)[(size_t)node * (OUT_F / 4) + q] = r;
}

extern "C" void kernel_launch(void* const* d_in, const int* in_sizes, int n_in,
                              void* d_out, int out_size)
{
    const float* X    = (const float*)d_in[0];
    const int*   rows = (const int*)  d_in[1];
    const int*   cols = (const int*)  d_in[2];
    const float* vals = (const float*)d_in[3];
    const float* W    = (const float*)d_in[4];
    const float* bias = (const float*)d_in[5];
    float*       out  = (float*)d_out;

    int n_nodes = in_sizes[0] / IN_F;
    int n_edges = in_sizes[1];

    float* S;      cudaGetSymbolAddress((void**)&S,      g_support);
    uint2* sorted; cudaGetSymbolAddress((void**)&sorted, g_sorted);
    int*   counts; cudaGetSymbolAddress((void**)&counts, g_counts);
    int*   rowptr; cudaGetSymbolAddress((void**)&rowptr, g_rowptr);
    int*   cursor; cudaGetSymbolAddress((void**)&cursor, g_cursor);

    // CSR build
    zero_counts_kernel<<<(n_nodes + 255) / 256, 256>>>(counts, n_nodes);
    hist_kernel<<<(n_edges + 255) / 256, 256>>>(rows, counts, n_edges);
    scan_kernel<<<1, 1024>>>(counts, rowptr, cursor, n_nodes);
    place_kernel<<<(n_edges + 255) / 256, 256>>>(rows, cols, vals, cursor,
                                                 sorted, n_edges);

    // dense: support = X @ W
    gemm_kernel<<<(n_nodes + 255) / 256, 256>>>(X, W, S, n_nodes);

    // fused gather + bias + relu (single non-atomic write per output row)
    long long total = (long long)n_nodes * 16;
    gather_kernel<<<(int)((total + 255) / 256), 256>>>(rowptr, counts, sorted,
                                                       S, bias, out, n_nodes);
}